// round 2
// baseline (speedup 1.0000x reference)
#include <cuda_runtime.h>
#include <cuda_bf16.h>
#include <math.h>

// Problem constants
// B=8, W=64 -> 512 windows; N=128 rows/window; D=1024; P=512; V=256
// out row stride = D + V = 1280 floats (320 float4)

#define NWIN   512
#define NROW   128
#define DDIM   1024
#define PDIM   512
#define VDIM   256
#define D4     256    // DDIM/4
#define OSTR4  320    // (DDIM+VDIM)/4

// ---------------- scratch (device globals; no allocation allowed) ----------
// layout (floats):
//  POS   [128*512]       pooled [512*1024]    we [512*512]   q [512*512]
//  qk    [512*1024]      qpos   [512*128]     xa [512*1024]  av [512*256]
#define OFF_POS    0
#define OFF_POOLED 65536
#define OFF_WE     589824
#define OFF_Q      851968
#define OFF_QK     1114112
#define OFF_QPOS   1638400
#define OFF_XA     1703936
#define OFF_AV     2228224
#define SCRATCH_SZ 2359296

__device__ float g_scratch[SCRATCH_SZ];
__device__ int   g_maskmode;   // 0 = int32 mask, 1 = byte mask

__device__ __forceinline__ int mask_at(const void* mask, int idx) {
    if (g_maskmode)
        return (int)((const unsigned char*)mask)[idx];
    return ((const int*)mask)[idx];
}

// ---------------- K0: sinusoidal position table + mask dtype detect --------
__global__ void pos_kernel(const float* __restrict__ pos_scale,
                           const unsigned int* __restrict__ mask_raw) {
    int idx = blockIdx.x * blockDim.x + threadIdx.x;   // 65536 threads
    if (idx == 0) {
        int mode = 0;
        for (int i = 0; i < 16; i++)
            if (mask_raw[i] > 1u) mode = 1;
        g_maskmode = mode;
    }
    if (idx >= NROW * PDIM) return;
    int j = idx / PDIM;
    int c = idx % PDIM;
    int i = c & 255;                                    // freq index
    float invf = powf(10000.0f, -((float)(2 * i)) / 512.0f);
    float ang  = (float)j * invf;
    float v    = (c < 256) ? sinf(ang) : cosf(ang);
    g_scratch[OFF_POS + idx] = v * pos_scale[0];
}

// ---------------- K1: masked mean pool + copy x into out[..., :1024] -------
__global__ void __launch_bounds__(256)
pooled_copy_kernel(const float* __restrict__ x, const void* __restrict__ mask,
                   float* __restrict__ out) {
    int win = blockIdx.x;
    int t   = threadIdx.x;                              // 256 threads
    __shared__ int   smask[NROW];
    __shared__ float slen;
    if (t < NROW) smask[t] = mask_at(mask, win * NROW + t);
    __syncthreads();
    if (t == 0) {
        int cnt = 0;
        for (int j = 0; j < NROW; j++) cnt += (smask[j] == 0);
        slen = fmaxf((float)cnt, 1.0f);
    }
    __syncthreads();

    const float4* x4 = (const float4*)x + (size_t)win * NROW * D4;
    float4* o4 = (float4*)out;
    float4 acc = make_float4(0.f, 0.f, 0.f, 0.f);
    size_t obase = (size_t)win * NROW * OSTR4 + t;
#pragma unroll 4
    for (int j = 0; j < NROW; j++) {
        float4 xv = __ldcs(&x4[j * D4 + t]);
        __stcs(&o4[obase + (size_t)j * OSTR4], xv);
        float m = (smask[j] == 0) ? 1.0f : 0.0f;
        acc.x += m * xv.x; acc.y += m * xv.y; acc.z += m * xv.z; acc.w += m * xv.w;
    }
    float inv = 1.0f / slen;
    float4 p = make_float4(acc.x * inv, acc.y * inv, acc.z * inv, acc.w * inv);
    ((float4*)(g_scratch + OFF_POOLED))[win * D4 + t] = p;
}

// ---------------- generic tiled fp32 GEMM: C[M,N] = act(A[M,K] @ B(^T)) ----
// dims all multiples of 64 (M,N) and 16 (K) in this problem; no guards.
template <bool TRANSB, bool RELU>
__global__ void __launch_bounds__(256)
gemm_kernel(const float* __restrict__ A, const float* __restrict__ Bm,
            float* __restrict__ C, int M, int Nn, int K) {
    __shared__ float sA[16][68];
    __shared__ float sB[16][68];
    int tid = threadIdx.x;
    int tx = tid % 16, ty = tid / 16;
    int bn = blockIdx.x * 64;
    int bm = blockIdx.y * 64;
    float c[4][4] = {};

    for (int k0 = 0; k0 < K; k0 += 16) {
        {   // A tile: k fastest for coalescing
            int ak = tid % 16, am = tid / 16;
#pragma unroll
            for (int r = 0; r < 4; r++) {
                int m = am + r * 16;
                sA[ak][m] = A[(size_t)(bm + m) * K + k0 + ak];
            }
        }
        if (!TRANSB) {
            int n = tid % 64, bk = tid / 64;
#pragma unroll
            for (int r = 0; r < 4; r++) {
                int k = bk + r * 4;
                sB[k][n] = Bm[(size_t)(k0 + k) * Nn + bn + n];
            }
        } else {
            int bk = tid % 16, nn = tid / 16;
#pragma unroll
            for (int r = 0; r < 4; r++) {
                int n = nn + r * 16;
                sB[bk][n] = Bm[(size_t)(bn + n) * K + k0 + bk];
            }
        }
        __syncthreads();
#pragma unroll
        for (int k = 0; k < 16; k++) {
            float4 av = *(const float4*)&sA[k][ty * 4];
            float4 bv = *(const float4*)&sB[k][tx * 4];
            float a[4] = {av.x, av.y, av.z, av.w};
            float b[4] = {bv.x, bv.y, bv.z, bv.w};
#pragma unroll
            for (int i = 0; i < 4; i++)
#pragma unroll
                for (int j = 0; j < 4; j++)
                    c[i][j] += a[i] * b[j];
        }
        __syncthreads();
    }
#pragma unroll
    for (int i = 0; i < 4; i++) {
        int m = bm + ty * 4 + i;
#pragma unroll
        for (int j = 0; j < 4; j++) {
            float v = c[i][j];
            if (RELU) v = fmaxf(v, 0.0f);
            C[(size_t)m * Nn + bn + tx * 4 + j] = v;
        }
    }
}

// ---------------- K3: per-window attention (dots -> softmax -> weighted sum)
// persistent grid so each window's 512KB x-slice stays L2-resident between
// the dots pass and the weighted-sum pass.
__global__ void __launch_bounds__(256)
attn_kernel(const float* __restrict__ x, const void* __restrict__ mask) {
    int t = threadIdx.x;
    int lane = t & 31, wp = t >> 5;                     // 8 warps
    __shared__ float4 s_qk[D4];
    __shared__ float  s_dots[NROW];
    __shared__ float  s_attn[NROW];
    __shared__ int    smask[NROW];

    for (int win = blockIdx.x; win < NWIN; win += gridDim.x) {
        s_qk[t] = ((const float4*)(g_scratch + OFF_QK))[win * D4 + t];
        if (t < NROW) smask[t] = mask_at(mask, win * NROW + t);
        __syncthreads();

        const float4* x4 = (const float4*)x + (size_t)win * NROW * D4;
        // phase 1: dots_j = (x_j . qk + qpos_j) * p^-0.5, masked
#pragma unroll 2
        for (int r = 0; r < 16; r++) {
            int j = r * 8 + wp;
            const float4* xr = x4 + j * D4;
            float p = 0.f;
#pragma unroll
            for (int kk = 0; kk < 8; kk++) {
                int i = kk * 32 + lane;
                float4 xv = xr[i];
                float4 qv = s_qk[i];
                p += xv.x * qv.x + xv.y * qv.y + xv.z * qv.z + xv.w * qv.w;
            }
#pragma unroll
            for (int off = 16; off; off >>= 1)
                p += __shfl_down_sync(0xffffffffu, p, off);
            if (lane == 0) {
                float dv = (p + g_scratch[OFF_QPOS + win * NROW + j]) *
                           0.04419417382415922f;       // 512^-0.5
                if (smask[j] != 0) dv = -3.4028234663852886e38f;
                s_dots[j] = dv;
            }
        }
        __syncthreads();
        // softmax over 128 values (warp 0)
        if (wp == 0) {
            float d0 = s_dots[lane],      d1 = s_dots[lane + 32];
            float d2 = s_dots[lane + 64], d3 = s_dots[lane + 96];
            float m = fmaxf(fmaxf(d0, d1), fmaxf(d2, d3));
#pragma unroll
            for (int off = 16; off; off >>= 1)
                m = fmaxf(m, __shfl_xor_sync(0xffffffffu, m, off));
            float e0 = expf(d0 - m), e1 = expf(d1 - m);
            float e2 = expf(d2 - m), e3 = expf(d3 - m);
            float s = e0 + e1 + e2 + e3;
#pragma unroll
            for (int off = 16; off; off >>= 1)
                s += __shfl_xor_sync(0xffffffffu, s, off);
            float inv = 1.0f / s;
            s_attn[lane]      = e0 * inv;
            s_attn[lane + 32] = e1 * inv;
            s_attn[lane + 64] = e2 * inv;
            s_attn[lane + 96] = e3 * inv;
        }
        __syncthreads();
        // phase 2: xa = sum_j attn_j * x_j   (re-read hits L2)
        float4 acc = make_float4(0.f, 0.f, 0.f, 0.f);
#pragma unroll 4
        for (int j = 0; j < NROW; j++) {
            float a = s_attn[j];
            float4 xv = __ldcs(&x4[j * D4 + t]);
            acc.x += a * xv.x; acc.y += a * xv.y;
            acc.z += a * xv.z; acc.w += a * xv.w;
        }
        ((float4*)(g_scratch + OFF_XA))[win * D4 + t] = acc;
        __syncthreads();
    }
}

// ---------------- K4: out[..., 1024:1280] = bos-shifted av, broadcast over n
__global__ void __launch_bounds__(256)
tail_kernel(const float* __restrict__ bos, float* __restrict__ out) {
    int win = blockIdx.x;
    int w = win & 63;
    int t = threadIdx.x;                                // 256
    __shared__ float4 s_av[64];
    if (t < 64) {
        s_av[t] = (w == 0) ? ((const float4*)bos)[t]
                           : ((const float4*)(g_scratch + OFF_AV))[(win - 1) * 64 + t];
    }
    __syncthreads();
    int c = t & 63;
    int jb = t >> 6;                                    // 0..3
    float4 v = s_av[c];
    float4* o4 = (float4*)out + (size_t)win * NROW * OSTR4 + 256;
#pragma unroll
    for (int r = 0; r < 32; r++) {
        int j = jb + r * 4;
        __stcs(&o4[(size_t)j * OSTR4 + c], v);
    }
}

// ---------------------------------------------------------------------------
extern "C" void kernel_launch(void* const* d_in, const int* in_sizes, int n_in,
                              void* d_out, int out_size) {
    const float* x    = (const float*)d_in[0];
    const void*  mask = d_in[1];
    const float* W_in = (const float*)d_in[2];
    const float* W_q  = (const float*)d_in[3];
    const float* W_k  = (const float*)d_in[4];
    const float* W_v  = (const float*)d_in[5];
    const float* ps   = (const float*)d_in[6];
    const float* bos  = (const float*)d_in[7];
    float* out = (float*)d_out;

    float* S = nullptr;
    cudaGetSymbolAddress((void**)&S, g_scratch);
    float* pPOS    = S + OFF_POS;
    float* pPOOLED = S + OFF_POOLED;
    float* pWE     = S + OFF_WE;
    float* pQ      = S + OFF_Q;
    float* pQK     = S + OFF_QK;
    float* pQPOS   = S + OFF_QPOS;
    float* pXA     = S + OFF_XA;
    float* pAV     = S + OFF_AV;

    // K0: pos table + mask dtype detection
    pos_kernel<<<128, 512>>>(ps, (const unsigned int*)mask);
    // K1: masked mean pool + copy x into out
    pooled_copy_kernel<<<NWIN, 256>>>(x, mask, out);
    // small GEMM chain (M = 512 windows)
    gemm_kernel<false, true ><<<dim3(8, 8),  256>>>(pPOOLED, W_in, pWE,   512, 512,  1024);
    gemm_kernel<false, false><<<dim3(8, 8),  256>>>(pWE,     W_q,  pQ,    512, 512,  512);
    gemm_kernel<true,  false><<<dim3(16, 8), 256>>>(pQ,      W_k,  pQK,   512, 1024, 512);
    gemm_kernel<true,  false><<<dim3(2, 8),  256>>>(pQ,      pPOS, pQPOS, 512, 128,  512);
    // K3: attention per window (persistent)
    attn_kernel<<<224, 256>>>(x, mask);
    // av = xa @ W_v
    gemm_kernel<false, false><<<dim3(4, 8),  256>>>(pXA,     W_v,  pAV,   512, 256,  1024);
    // K4: bos-shifted broadcast into out[..., 1024:]
    tail_kernel<<<NWIN, 256>>>(bos, out);
}

// round 13
// speedup vs baseline: 1.4684x; 1.4684x over previous
#include <cuda_runtime.h>
#include <cuda_bf16.h>
#include <math.h>

// B=8, W=64 -> 512 windows; N=128 rows/window; D=1024; P=512; V=256
// out row stride = D + V = 1280 floats (320 float4)

#define NWIN   512
#define NROW   128
#define DDIM   1024
#define PDIM   512
#define VDIM   256
#define D4     256    // DDIM/4
#define OSTR4  320    // (DDIM+VDIM)/4

// ---------------- scratch (device globals; no allocation allowed) ----------
// floats. GEMM outputs [WE..AV] are contiguous so one memset zeroes them all.
#define OFF_POS    0          // 128*512
#define OFF_POOLED 65536      // 512*1024
#define OFF_XA     589824     // 512*1024
#define OFF_WE     1114112    // 512*512   (raw, pre-relu)
#define OFF_Q      1376256    // 512*512
#define OFF_QK     1638400    // 512*1024
#define OFF_QPOS   2162688    // 512*128
#define OFF_AV     2228224    // 512*256
#define SCRATCH_SZ 2359296
#define GEMMOUT_FLOATS (SCRATCH_SZ - OFF_WE)   // 1245184

__device__ float g_scratch[SCRATCH_SZ];
__device__ int   g_maskmode;   // 0 = int32 mask, 1 = byte mask

__device__ __forceinline__ int mask_at(const void* mask, int idx) {
    if (g_maskmode)
        return (int)((const unsigned char*)mask)[idx];
    return ((const int*)mask)[idx];
}

// ---------------- K0: sinusoidal position table + mask dtype detect --------
__global__ void pos_kernel(const float* __restrict__ pos_scale,
                           const unsigned int* __restrict__ mask_raw) {
    int idx = blockIdx.x * blockDim.x + threadIdx.x;   // 65536 threads
    if (idx == 0) {
        int mode = 0;
        for (int i = 0; i < 16; i++)
            if (mask_raw[i] > 1u) mode = 1;
        g_maskmode = mode;
    }
    if (idx >= NROW * PDIM) return;
    int j = idx / PDIM;
    int c = idx % PDIM;
    int i = c & 255;                                    // freq index
    float invf = powf(10000.0f, -((float)(2 * i)) / 512.0f);
    float ang  = (float)j * invf;
    float v    = (c < 256) ? sinf(ang) : cosf(ang);
    g_scratch[OFF_POS + idx] = v * pos_scale[0];
}

// ---------------- K1: masked mean pool + copy x into out[..., :1024] -------
__global__ void __launch_bounds__(256)
pooled_copy_kernel(const float* __restrict__ x, const void* __restrict__ mask,
                   float* __restrict__ out) {
    int win = blockIdx.x;
    int t   = threadIdx.x;                              // 256 threads
    __shared__ int   smask[NROW];
    __shared__ float slen;
    if (t < NROW) smask[t] = mask_at(mask, win * NROW + t);
    __syncthreads();
    if (t == 0) {
        int cnt = 0;
        for (int j = 0; j < NROW; j++) cnt += (smask[j] == 0);
        slen = fmaxf((float)cnt, 1.0f);
    }
    __syncthreads();

    const float4* x4 = (const float4*)x + (size_t)win * NROW * D4;
    float4* o4 = (float4*)out;
    float4 acc = make_float4(0.f, 0.f, 0.f, 0.f);
    size_t obase = (size_t)win * NROW * OSTR4 + t;
#pragma unroll 4
    for (int j = 0; j < NROW; j++) {
        float4 xv = __ldcs(&x4[j * D4 + t]);
        __stcs(&o4[obase + (size_t)j * OSTR4], xv);
        float m = (smask[j] == 0) ? 1.0f : 0.0f;
        acc.x += m * xv.x; acc.y += m * xv.y; acc.z += m * xv.z; acc.w += m * xv.w;
    }
    float inv = 1.0f / slen;
    float4 p = make_float4(acc.x * inv, acc.y * inv, acc.z * inv, acc.w * inv);
    ((float4*)(g_scratch + OFF_POOLED))[win * D4 + t] = p;
}

// ---------------- split-K tiled fp32 GEMM, atomicAdd accumulate ------------
// C[M,N] += A'[M,K-chunk] @ B(^T)[K-chunk,N], A' = relu(A) if RELUA.
// grid = (N/64, M/64, K/KC). C must be zeroed before the launch chain.
// M,N multiples of 64; K,KC multiples of 16.
template <bool TRANSB, bool RELUA>
__global__ void __launch_bounds__(256)
gemm_splitk_kernel(const float* __restrict__ A, const float* __restrict__ Bm,
                   float* __restrict__ C, int M, int Nn, int K, int KC) {
    __shared__ float sA[16][68];
    __shared__ float sB[16][68];
    int tid = threadIdx.x;
    int tx = tid % 16, ty = tid / 16;
    int bn = blockIdx.x * 64;
    int bm = blockIdx.y * 64;
    int kbeg = blockIdx.z * KC;
    int kend = kbeg + KC;
    float c[4][4] = {};

    for (int k0 = kbeg; k0 < kend; k0 += 16) {
        {   // A tile: k fastest for coalescing
            int ak = tid % 16, am = tid / 16;
#pragma unroll
            for (int r = 0; r < 4; r++) {
                int m = am + r * 16;
                float v = A[(size_t)(bm + m) * K + k0 + ak];
                if (RELUA) v = fmaxf(v, 0.0f);
                sA[ak][m] = v;
            }
        }
        if (!TRANSB) {
            int n = tid % 64, bk = tid / 64;
#pragma unroll
            for (int r = 0; r < 4; r++) {
                int k = bk + r * 4;
                sB[k][n] = Bm[(size_t)(k0 + k) * Nn + bn + n];
            }
        } else {
            int bk = tid % 16, nn = tid / 16;
#pragma unroll
            for (int r = 0; r < 4; r++) {
                int n = nn + r * 16;
                sB[bk][n] = Bm[(size_t)(bn + n) * K + k0 + bk];
            }
        }
        __syncthreads();
#pragma unroll
        for (int k = 0; k < 16; k++) {
            float4 av = *(const float4*)&sA[k][ty * 4];
            float4 bv = *(const float4*)&sB[k][tx * 4];
            float a[4] = {av.x, av.y, av.z, av.w};
            float b[4] = {bv.x, bv.y, bv.z, bv.w};
#pragma unroll
            for (int i = 0; i < 4; i++)
#pragma unroll
                for (int j = 0; j < 4; j++)
                    c[i][j] += a[i] * b[j];
        }
        __syncthreads();
    }
#pragma unroll
    for (int i = 0; i < 4; i++) {
        int m = bm + ty * 4 + i;
#pragma unroll
        for (int j = 0; j < 4; j++)
            atomicAdd(&C[(size_t)m * Nn + bn + tx * 4 + j], c[i][j]);
    }
}

// ---------------- K3: per-window attention (dots -> softmax -> weighted sum)
__global__ void __launch_bounds__(256)
attn_kernel(const float* __restrict__ x, const void* __restrict__ mask) {
    int t = threadIdx.x;
    int lane = t & 31, wp = t >> 5;                     // 8 warps
    __shared__ float4 s_qk[D4];
    __shared__ float  s_dots[NROW];
    __shared__ float  s_attn[NROW];
    __shared__ int    smask[NROW];

    for (int win = blockIdx.x; win < NWIN; win += gridDim.x) {
        s_qk[t] = ((const float4*)(g_scratch + OFF_QK))[win * D4 + t];
        if (t < NROW) smask[t] = mask_at(mask, win * NROW + t);
        __syncthreads();

        const float4* x4 = (const float4*)x + (size_t)win * NROW * D4;
        // phase 1: dots_j = (x_j . qk + qpos_j) * p^-0.5, masked
#pragma unroll 2
        for (int r = 0; r < 16; r++) {
            int j = r * 8 + wp;
            const float4* xr = x4 + j * D4;
            float p = 0.f;
#pragma unroll
            for (int kk = 0; kk < 8; kk++) {
                int i = kk * 32 + lane;
                float4 xv = xr[i];
                float4 qv = s_qk[i];
                p += xv.x * qv.x + xv.y * qv.y + xv.z * qv.z + xv.w * qv.w;
            }
#pragma unroll
            for (int off = 16; off; off >>= 1)
                p += __shfl_down_sync(0xffffffffu, p, off);
            if (lane == 0) {
                float dv = (p + g_scratch[OFF_QPOS + win * NROW + j]) *
                           0.04419417382415922f;       // 512^-0.5
                if (smask[j] != 0) dv = -3.4028234663852886e38f;
                s_dots[j] = dv;
            }
        }
        __syncthreads();
        // softmax over 128 values (warp 0)
        if (wp == 0) {
            float d0 = s_dots[lane],      d1 = s_dots[lane + 32];
            float d2 = s_dots[lane + 64], d3 = s_dots[lane + 96];
            float m = fmaxf(fmaxf(d0, d1), fmaxf(d2, d3));
#pragma unroll
            for (int off = 16; off; off >>= 1)
                m = fmaxf(m, __shfl_xor_sync(0xffffffffu, m, off));
            float e0 = expf(d0 - m), e1 = expf(d1 - m);
            float e2 = expf(d2 - m), e3 = expf(d3 - m);
            float s = e0 + e1 + e2 + e3;
#pragma unroll
            for (int off = 16; off; off >>= 1)
                s += __shfl_xor_sync(0xffffffffu, s, off);
            float inv = 1.0f / s;
            s_attn[lane]      = e0 * inv;
            s_attn[lane + 32] = e1 * inv;
            s_attn[lane + 64] = e2 * inv;
            s_attn[lane + 96] = e3 * inv;
        }
        __syncthreads();
        // phase 2: xa = sum_j attn_j * x_j   (re-read hits L2)
        float4 acc = make_float4(0.f, 0.f, 0.f, 0.f);
#pragma unroll 4
        for (int j = 0; j < NROW; j++) {
            float a = s_attn[j];
            float4 xv = __ldcs(&x4[j * D4 + t]);
            acc.x += a * xv.x; acc.y += a * xv.y;
            acc.z += a * xv.z; acc.w += a * xv.w;
        }
        ((float4*)(g_scratch + OFF_XA))[win * D4 + t] = acc;
        __syncthreads();
    }
}

// ---------------- K4: out[..., 1024:1280] = bos-shifted av, broadcast over n
__global__ void __launch_bounds__(256)
tail_kernel(const float* __restrict__ bos, float* __restrict__ out) {
    int win = blockIdx.x;
    int w = win & 63;
    int t = threadIdx.x;                                // 256
    __shared__ float4 s_av[64];
    if (t < 64) {
        s_av[t] = (w == 0) ? ((const float4*)bos)[t]
                           : ((const float4*)(g_scratch + OFF_AV))[(win - 1) * 64 + t];
    }
    __syncthreads();
    int c = t & 63;
    int jb = t >> 6;                                    // 0..3
    float4 v = s_av[c];
    float4* o4 = (float4*)out + (size_t)win * NROW * OSTR4 + 256;
#pragma unroll
    for (int r = 0; r < 32; r++) {
        int j = jb + r * 4;
        __stcs(&o4[(size_t)j * OSTR4 + c], v);
    }
}

// ---------------------------------------------------------------------------
extern "C" void kernel_launch(void* const* d_in, const int* in_sizes, int n_in,
                              void* d_out, int out_size) {
    const float* x    = (const float*)d_in[0];
    const void*  mask = d_in[1];
    const float* W_in = (const float*)d_in[2];
    const float* W_q  = (const float*)d_in[3];
    const float* W_k  = (const float*)d_in[4];
    const float* W_v  = (const float*)d_in[5];
    const float* ps   = (const float*)d_in[6];
    const float* bos  = (const float*)d_in[7];
    float* out = (float*)d_out;

    float* S = nullptr;
    cudaGetSymbolAddress((void**)&S, g_scratch);
    float* pPOS    = S + OFF_POS;
    float* pPOOLED = S + OFF_POOLED;
    float* pXA     = S + OFF_XA;
    float* pWE     = S + OFF_WE;
    float* pQ      = S + OFF_Q;
    float* pQK     = S + OFF_QK;
    float* pQPOS   = S + OFF_QPOS;
    float* pAV     = S + OFF_AV;

    // zero all split-K GEMM outputs (contiguous block), graph-capturable
    cudaMemsetAsync(pWE, 0, (size_t)GEMMOUT_FLOATS * sizeof(float));

    // K0: pos table + mask dtype detection
    pos_kernel<<<128, 512>>>(ps, (const unsigned int*)mask);
    // K1: masked mean pool + copy x into out
    pooled_copy_kernel<<<NWIN, 256>>>(x, mask, out);

    // split-K GEMM chain (M = 512 windows). ReLU folded into GEMM2's A load.
    // weRaw = pooled @ W_in            [512,512]  K=1024, 4 splits -> 256 blocks
    gemm_splitk_kernel<false, false><<<dim3(8, 8, 4),  256>>>(pPOOLED, W_in, pWE,   512, 512,  1024, 256);
    // q = relu(weRaw) @ W_q            [512,512]  K=512,  4 splits -> 256 blocks
    gemm_splitk_kernel<false, true ><<<dim3(8, 8, 4),  256>>>(pWE,     W_q,  pQ,    512, 512,  512,  128);
    // qk = q @ W_k^T                   [512,1024] K=512,  4 splits -> 512 blocks
    gemm_splitk_kernel<true,  false><<<dim3(16, 8, 4), 256>>>(pQ,      W_k,  pQK,   512, 1024, 512,  128);
    // qpos = q @ pos^T                 [512,128]  K=512,  8 splits -> 128 blocks
    gemm_splitk_kernel<true,  false><<<dim3(2, 8, 8),  256>>>(pQ,      pPOS, pQPOS, 512, 128,  512,  64);

    // K3: attention per window (persistent)
    attn_kernel<<<224, 256>>>(x, mask);

    // av = xa @ W_v                    [512,256]  K=1024, 4 splits -> 128 blocks
    gemm_splitk_kernel<false, false><<<dim3(4, 8, 4),  256>>>(pXA,     W_v,  pAV,   512, 256,  1024, 256);

    // K4: bos-shifted broadcast into out[..., 1024:]
    tail_kernel<<<NWIN, 256>>>(bos, out);
}

// round 16
// speedup vs baseline: 1.4715x; 1.0021x over previous
#include <cuda_runtime.h>
#include <cuda_bf16.h>
#include <math.h>

// B=8, W=64 -> 512 windows; N=128 rows/window; D=1024; P=512; V=256
// out row stride = D + V = 1280 floats (320 float4)

#define NWIN   512
#define NROW   128
#define DDIM   1024
#define PDIM   512
#define VDIM   256
#define D4     256    // DDIM/4
#define OSTR4  320    // (DDIM+VDIM)/4

// ---------------- scratch (device globals; no allocation allowed) ----------
// floats. GEMM outputs [WE..AV] are contiguous so one memset zeroes them all.
#define OFF_POS    0          // 128*512
#define OFF_POOLED 65536      // 512*1024
#define OFF_XA     589824     // 512*1024
#define OFF_WE     1114112    // 512*512   (raw, pre-relu)
#define OFF_Q      1376256    // 512*512
#define OFF_QK     1638400    // 512*1024
#define OFF_QPOS   2162688    // 512*128
#define OFF_AV     2228224    // 512*256
#define SCRATCH_SZ 2359296
#define GEMMOUT_FLOATS (SCRATCH_SZ - OFF_WE)   // 1245184

__device__ float g_scratch[SCRATCH_SZ];
__device__ int   g_maskmode;   // 0 = int32 mask, 1 = byte mask

__device__ __forceinline__ int mask_at(const void* mask, int idx) {
    if (g_maskmode)
        return (int)((const unsigned char*)mask)[idx];
    return ((const int*)mask)[idx];
}

// ---------------- K0: sinusoidal position table + mask dtype detect --------
__global__ void pos_kernel(const float* __restrict__ pos_scale,
                           const unsigned int* __restrict__ mask_raw) {
    int idx = blockIdx.x * blockDim.x + threadIdx.x;   // 65536 threads
    if (idx == 0) {
        int mode = 0;
        for (int i = 0; i < 16; i++)
            if (mask_raw[i] > 1u) mode = 1;
        g_maskmode = mode;
    }
    if (idx >= NROW * PDIM) return;
    int j = idx / PDIM;
    int c = idx % PDIM;
    int i = c & 255;                                    // freq index
    float invf = powf(10000.0f, -((float)(2 * i)) / 512.0f);
    float ang  = (float)j * invf;
    float v    = (c < 256) ? sinf(ang) : cosf(ang);
    g_scratch[OFF_POS + idx] = v * pos_scale[0];
}

// ---------------- K1: masked mean pool + copy x into out[..., :1024] -------
__global__ void __launch_bounds__(256)
pooled_copy_kernel(const float* __restrict__ x, const void* __restrict__ mask,
                   float* __restrict__ out) {
    int win = blockIdx.x;
    int t   = threadIdx.x;                              // 256 threads
    __shared__ int   smask[NROW];
    __shared__ float slen;
    if (t < NROW) smask[t] = mask_at(mask, win * NROW + t);
    __syncthreads();
    if (t == 0) {
        int cnt = 0;
        for (int j = 0; j < NROW; j++) cnt += (smask[j] == 0);
        slen = fmaxf((float)cnt, 1.0f);
    }
    __syncthreads();

    const float4* x4 = (const float4*)x + (size_t)win * NROW * D4;
    float4* o4 = (float4*)out;
    float4 acc = make_float4(0.f, 0.f, 0.f, 0.f);
    size_t obase = (size_t)win * NROW * OSTR4 + t;
#pragma unroll 4
    for (int j = 0; j < NROW; j++) {
        float4 xv = __ldcs(&x4[j * D4 + t]);
        __stcs(&o4[obase + (size_t)j * OSTR4], xv);
        float m = (smask[j] == 0) ? 1.0f : 0.0f;
        acc.x += m * xv.x; acc.y += m * xv.y; acc.z += m * xv.z; acc.w += m * xv.w;
    }
    float inv = 1.0f / slen;
    float4 p = make_float4(acc.x * inv, acc.y * inv, acc.z * inv, acc.w * inv);
    ((float4*)(g_scratch + OFF_POOLED))[win * D4 + t] = p;
}

// ---------------- split-K tiled fp32 GEMM, atomicAdd accumulate ------------
// C[M,N] += A'[M,K-chunk] @ B(^T)[K-chunk,N], A' = relu(A) if RELUA.
// grid = (N/64, M/64, K/KC). C must be zeroed before the launch chain.
// M,N multiples of 64; K,KC multiples of 16.
template <bool TRANSB, bool RELUA>
__global__ void __launch_bounds__(256)
gemm_splitk_kernel(const float* __restrict__ A, const float* __restrict__ Bm,
                   float* __restrict__ C, int M, int Nn, int K, int KC) {
    __shared__ float sA[16][68];
    __shared__ float sB[16][68];
    int tid = threadIdx.x;
    int tx = tid % 16, ty = tid / 16;
    int bn = blockIdx.x * 64;
    int bm = blockIdx.y * 64;
    int kbeg = blockIdx.z * KC;
    int kend = kbeg + KC;
    float c[4][4] = {};

    for (int k0 = kbeg; k0 < kend; k0 += 16) {
        {   // A tile: k fastest for coalescing
            int ak = tid % 16, am = tid / 16;
#pragma unroll
            for (int r = 0; r < 4; r++) {
                int m = am + r * 16;
                float v = A[(size_t)(bm + m) * K + k0 + ak];
                if (RELUA) v = fmaxf(v, 0.0f);
                sA[ak][m] = v;
            }
        }
        if (!TRANSB) {
            int n = tid % 64, bk = tid / 64;
#pragma unroll
            for (int r = 0; r < 4; r++) {
                int k = bk + r * 4;
                sB[k][n] = Bm[(size_t)(k0 + k) * Nn + bn + n];
            }
        } else {
            int bk = tid % 16, nn = tid / 16;
#pragma unroll
            for (int r = 0; r < 4; r++) {
                int n = nn + r * 16;
                sB[bk][n] = Bm[(size_t)(bn + n) * K + k0 + bk];
            }
        }
        __syncthreads();
#pragma unroll
        for (int k = 0; k < 16; k++) {
            float4 av = *(const float4*)&sA[k][ty * 4];
            float4 bv = *(const float4*)&sB[k][tx * 4];
            float a[4] = {av.x, av.y, av.z, av.w};
            float b[4] = {bv.x, bv.y, bv.z, bv.w};
#pragma unroll
            for (int i = 0; i < 4; i++)
#pragma unroll
                for (int j = 0; j < 4; j++)
                    c[i][j] += a[i] * b[j];
        }
        __syncthreads();
    }
#pragma unroll
    for (int i = 0; i < 4; i++) {
        int m = bm + ty * 4 + i;
#pragma unroll
        for (int j = 0; j < 4; j++)
            atomicAdd(&C[(size_t)m * Nn + bn + tx * 4 + j], c[i][j]);
    }
}

// ---------------- K3: per-window attention (dots -> softmax -> weighted sum)
__global__ void __launch_bounds__(256)
attn_kernel(const float* __restrict__ x, const void* __restrict__ mask) {
    int t = threadIdx.x;
    int lane = t & 31, wp = t >> 5;                     // 8 warps
    __shared__ float4 s_qk[D4];
    __shared__ float  s_dots[NROW];
    __shared__ float  s_attn[NROW];
    __shared__ int    smask[NROW];

    for (int win = blockIdx.x; win < NWIN; win += gridDim.x) {
        s_qk[t] = ((const float4*)(g_scratch + OFF_QK))[win * D4 + t];
        if (t < NROW) smask[t] = mask_at(mask, win * NROW + t);
        __syncthreads();

        const float4* x4 = (const float4*)x + (size_t)win * NROW * D4;
        // phase 1: dots_j = (x_j . qk + qpos_j) * p^-0.5, masked
#pragma unroll 2
        for (int r = 0; r < 16; r++) {
            int j = r * 8 + wp;
            const float4* xr = x4 + j * D4;
            float p = 0.f;
#pragma unroll
            for (int kk = 0; kk < 8; kk++) {
                int i = kk * 32 + lane;
                float4 xv = xr[i];
                float4 qv = s_qk[i];
                p += xv.x * qv.x + xv.y * qv.y + xv.z * qv.z + xv.w * qv.w;
            }
#pragma unroll
            for (int off = 16; off; off >>= 1)
                p += __shfl_down_sync(0xffffffffu, p, off);
            if (lane == 0) {
                float dv = (p + g_scratch[OFF_QPOS + win * NROW + j]) *
                           0.04419417382415922f;       // 512^-0.5
                if (smask[j] != 0) dv = -3.4028234663852886e38f;
                s_dots[j] = dv;
            }
        }
        __syncthreads();
        // softmax over 128 values (warp 0)
        if (wp == 0) {
            float d0 = s_dots[lane],      d1 = s_dots[lane + 32];
            float d2 = s_dots[lane + 64], d3 = s_dots[lane + 96];
            float m = fmaxf(fmaxf(d0, d1), fmaxf(d2, d3));
#pragma unroll
            for (int off = 16; off; off >>= 1)
                m = fmaxf(m, __shfl_xor_sync(0xffffffffu, m, off));
            float e0 = expf(d0 - m), e1 = expf(d1 - m);
            float e2 = expf(d2 - m), e3 = expf(d3 - m);
            float s = e0 + e1 + e2 + e3;
#pragma unroll
            for (int off = 16; off; off >>= 1)
                s += __shfl_xor_sync(0xffffffffu, s, off);
            float inv = 1.0f / s;
            s_attn[lane]      = e0 * inv;
            s_attn[lane + 32] = e1 * inv;
            s_attn[lane + 64] = e2 * inv;
            s_attn[lane + 96] = e3 * inv;
        }
        __syncthreads();
        // phase 2: xa = sum_j attn_j * x_j   (re-read hits L2)
        float4 acc = make_float4(0.f, 0.f, 0.f, 0.f);
#pragma unroll 4
        for (int j = 0; j < NROW; j++) {
            float a = s_attn[j];
            float4 xv = __ldcs(&x4[j * D4 + t]);
            acc.x += a * xv.x; acc.y += a * xv.y;
            acc.z += a * xv.z; acc.w += a * xv.w;
        }
        ((float4*)(g_scratch + OFF_XA))[win * D4 + t] = acc;
        __syncthreads();
    }
}

// ---------------- K4: out[..., 1024:1280] = bos-shifted av, broadcast over n
__global__ void __launch_bounds__(256)
tail_kernel(const float* __restrict__ bos, float* __restrict__ out) {
    int win = blockIdx.x;
    int w = win & 63;
    int t = threadIdx.x;                                // 256
    __shared__ float4 s_av[64];
    if (t < 64) {
        s_av[t] = (w == 0) ? ((const float4*)bos)[t]
                           : ((const float4*)(g_scratch + OFF_AV))[(win - 1) * 64 + t];
    }
    __syncthreads();
    int c = t & 63;
    int jb = t >> 6;                                    // 0..3
    float4 v = s_av[c];
    float4* o4 = (float4*)out + (size_t)win * NROW * OSTR4 + 256;
#pragma unroll
    for (int r = 0; r < 32; r++) {
        int j = jb + r * 4;
        __stcs(&o4[(size_t)j * OSTR4 + c], v);
    }
}

// ---------------------------------------------------------------------------
extern "C" void kernel_launch(void* const* d_in, const int* in_sizes, int n_in,
                              void* d_out, int out_size) {
    const float* x    = (const float*)d_in[0];
    const void*  mask = d_in[1];
    const float* W_in = (const float*)d_in[2];
    const float* W_q  = (const float*)d_in[3];
    const float* W_k  = (const float*)d_in[4];
    const float* W_v  = (const float*)d_in[5];
    const float* ps   = (const float*)d_in[6];
    const float* bos  = (const float*)d_in[7];
    float* out = (float*)d_out;

    float* S = nullptr;
    cudaGetSymbolAddress((void**)&S, g_scratch);
    float* pPOS    = S + OFF_POS;
    float* pPOOLED = S + OFF_POOLED;
    float* pXA     = S + OFF_XA;
    float* pWE     = S + OFF_WE;
    float* pQ      = S + OFF_Q;
    float* pQK     = S + OFF_QK;
    float* pQPOS   = S + OFF_QPOS;
    float* pAV     = S + OFF_AV;

    // zero all split-K GEMM outputs (contiguous block), graph-capturable
    cudaMemsetAsync(pWE, 0, (size_t)GEMMOUT_FLOATS * sizeof(float));

    // K0: pos table + mask dtype detection
    pos_kernel<<<128, 512>>>(ps, (const unsigned int*)mask);
    // K1: masked mean pool + copy x into out
    pooled_copy_kernel<<<NWIN, 256>>>(x, mask, out);

    // split-K GEMM chain (M = 512 windows). ReLU folded into GEMM2's A load.
    // Splits doubled vs R13: occ was 20.6% (grid-limited) at 256 blocks.
    // weRaw = pooled @ W_in            [512,512]  K=1024, 8 splits -> 512 blocks
    gemm_splitk_kernel<false, false><<<dim3(8, 8, 8),   256>>>(pPOOLED, W_in, pWE,   512, 512,  1024, 128);
    // q = relu(weRaw) @ W_q            [512,512]  K=512,  8 splits -> 512 blocks
    gemm_splitk_kernel<false, true ><<<dim3(8, 8, 8),   256>>>(pWE,     W_q,  pQ,    512, 512,  512,  64);
    // qk = q @ W_k^T                   [512,1024] K=512,  8 splits -> 1024 blocks
    gemm_splitk_kernel<true,  false><<<dim3(16, 8, 8),  256>>>(pQ,      W_k,  pQK,   512, 1024, 512,  64);
    // qpos = q @ pos^T                 [512,128]  K=512, 16 splits -> 256 blocks
    gemm_splitk_kernel<true,  false><<<dim3(2, 8, 16),  256>>>(pQ,      pPOS, pQPOS, 512, 128,  512,  32);

    // K3: attention per window (persistent)
    attn_kernel<<<224, 256>>>(x, mask);

    // av = xa @ W_v                    [512,256]  K=1024, 8 splits -> 256 blocks
    gemm_splitk_kernel<false, false><<<dim3(4, 8, 8),   256>>>(pXA,     W_v,  pAV,   512, 256,  1024, 128);

    // K4: bos-shifted broadcast into out[..., 1024:]
    tail_kernel<<<NWIN, 256>>>(bos, out);
}